// round 14
// baseline (speedup 1.0000x reference)
#include <cuda_runtime.h>
#include <cstdint>

#define MUL 32
#define N_NODES 50000
#define E_FEAT 224
#define CAP 64                    // bucket capacity per node (Poisson(16) max ~45)
#define SPILL_CAP 8192
#define MAX_E  2097152
#define INV_S2f 0.70710678118654752f
#define INV_S3f 0.57735026918962576f

__device__ int   g_idx_is_64;
__device__ int   g_cnt[N_NODES];             // per-node cursor / degree (self-cleaned by gather)
__device__ int   g_spill_cnt;
__device__ int4  g_spill[SPILL_CAP];         // (e, dst, src, 0) overflow edges
__device__ int2  g_es[N_NODES * CAP];        // (edge id, src) bucket slots
__device__ float g_xt[N_NODES * 4 * MUL];    // x transposed: [xs0|x1a|x1b|x1c]

__device__ __forceinline__ long long load_index(const void* p, int e, int is64) {
    if (is64) return ((const long long*)p)[e];
    return (long long)(__ldcs((const int*)p + e));
}

// k0: tiny detect kernel — index dtype probe + spill-count reset (1 warp).
__global__ void k_detect(const unsigned int* __restrict__ dw,
                         const unsigned int* __restrict__ sw) {
    if (threadIdx.x == 0) {
        g_spill_cnt = 0;
        // int64 little-endian values < 50000 -> every odd 32-bit word is 0.
        int is64 = 1;
        #pragma unroll
        for (int k = 0; k < 32; k++) {
            if (dw[2 * k + 1] != 0u || sw[2 * k + 1] != 0u) { is64 = 0; break; }
        }
        g_idx_is_64 = is64;
    }
}

__device__ __forceinline__ void place_edge(int e, int d, int s) {
    if ((unsigned)d < (unsigned)N_NODES) {
        int c = atomicAdd(&g_cnt[d], 1);
        if (c < CAP) {
            g_es[d * CAP + c] = make_int2(e, s);
        } else {
            int sp = atomicAdd(&g_spill_cnt, 1);
            if (sp < SPILL_CAP) g_spill[sp] = make_int4(e, d, s, 0);
        }
    }
}

// k1: bucket-place (8 edges/thread, vectorized int4 index loads on the int32
// path) + x transpose (warp/node).
__global__ __launch_bounds__(256)
void k_place_transpose(const void* __restrict__ edge_dst,
                       const void* __restrict__ edge_src,
                       const float* __restrict__ x, int E) {
    const int t = blockIdx.x * blockDim.x + threadIdx.x;
    const int is64 = g_idx_is_64;
    const int base = t * 8;
    if (base < E) {
        if (!is64 && base + 7 < E && ((base & 3) == 0)) {
            const int4* __restrict__ d4 = (const int4*)edge_dst;
            const int4* __restrict__ s4 = (const int4*)edge_src;
            const int4 da = __ldcs(&d4[t * 2]);
            const int4 db = __ldcs(&d4[t * 2 + 1]);
            const int4 sa = __ldcs(&s4[t * 2]);
            const int4 sb = __ldcs(&s4[t * 2 + 1]);
            place_edge(base + 0, da.x, sa.x);
            place_edge(base + 1, da.y, sa.y);
            place_edge(base + 2, da.z, sa.z);
            place_edge(base + 3, da.w, sa.w);
            place_edge(base + 4, db.x, sb.x);
            place_edge(base + 5, db.y, sb.y);
            place_edge(base + 6, db.z, sb.z);
            place_edge(base + 7, db.w, sb.w);
        } else {
            #pragma unroll
            for (int k = 0; k < 8; k++) {
                int e = base + k;
                if (e < E) {
                    long long d = load_index(edge_dst, e, is64);
                    long long s = (unsigned long long)d < (unsigned long long)N_NODES
                                  ? load_index(edge_src, e, is64) : 0;
                    place_edge(e, (int)d, (int)s);
                }
            }
        }
    }
    const int warp = threadIdx.x >> 5;
    const int lane = threadIdx.x & 31;
    const int n = blockIdx.x * 8 + warp;
    if (n < N_NODES) {
        const float* __restrict__ xr = x + (size_t)n * (4 * MUL);
        float xs0 = __ldcs(xr + lane);
        float x1a = __ldcs(xr + 32 + lane * 3 + 0);
        float x1b = __ldcs(xr + 32 + lane * 3 + 1);
        float x1c = __ldcs(xr + 32 + lane * 3 + 2);
        float* __restrict__ xt = g_xt + (size_t)n * (4 * MUL);
        xt[lane]      = xs0;
        xt[32 + lane] = x1a;
        xt[64 + lane] = x1b;
        xt[96 + lane] = x1c;
    }
}

__device__ __forceinline__ void edge_accum(
    int e, int s, int lane,
    const float* __restrict__ attr, const float* __restrict__ w,
    float& a0, float& a1a, float& a1b, float& a1c,
    float& a2a, float& a2b, float& a2c)
{
    const float* __restrict__ xr = g_xt + (size_t)s * (4 * MUL);
    const float xs0 = __ldg(xr + lane);
    const float x1a = __ldg(xr + 32 + lane);
    const float x1b = __ldg(xr + 64 + lane);
    const float x1c = __ldg(xr + 96 + lane);

    const float4 a = __ldg(reinterpret_cast<const float4*>(attr + (size_t)e * 4));

    const float* __restrict__ wr = w + (size_t)e * (5 * MUL);
    const float w0 = __ldcs(wr + lane);
    const float w1 = __ldcs(wr + 32 + lane);
    const float w2 = __ldcs(wr + 64 + lane);
    const float w3 = __ldcs(wr + 96 + lane);
    const float w4 = __ldcs(wr + 128 + lane);

    const float dot = x1a * a.y + x1b * a.z + x1c * a.w;
    a0  += w0 * xs0 * a.x + w3 * (INV_S3f * dot);
    a1a += w1 * xs0 * a.y + w2 * x1a * a.x;
    a1b += w1 * xs0 * a.z + w2 * x1b * a.x;
    a1c += w1 * xs0 * a.w + w2 * x1c * a.x;
    a2a += w4 * (x1b * a.w - x1c * a.z);
    a2b += w4 * (x1c * a.y - x1a * a.w);
    a2c += w4 * (x1a * a.z - x1b * a.y);
}

// k2: ONE WARP PER BLOCK gather (unchanged R13 hot path) + cursor self-clean.
__global__ __launch_bounds__(32)
void k_gather(const float* __restrict__ attr,
              const float* __restrict__ w,
              float* __restrict__ out) {
    const unsigned FULL = 0xffffffffu;
    const int lane = threadIdx.x;
    const int n = blockIdx.x;
    if (n >= N_NODES) return;

    int deg = __ldg(&g_cnt[n]);
    if (lane == 0) g_cnt[n] = 0;        // self-clean for next graph replay
    if (deg > CAP) deg = CAP;           // overflow handled via spill scan
    const int2* __restrict__ bucket = g_es + (size_t)n * CAP;

    float p0 = 0.f, p1a = 0.f, p1b = 0.f, p1c = 0.f, p2a = 0.f, p2b = 0.f, p2c = 0.f;
    float q0 = 0.f, q1a = 0.f, q1b = 0.f, q1c = 0.f, q2a = 0.f, q2b = 0.f, q2c = 0.f;

    for (int base = 0; base < deg; base += 32) {
        int m = deg - base; if (m > 32) m = 32;
        int2 es = make_int2(0, 0);
        if (lane < m) es = __ldg(&bucket[base + lane]);   // coalesced prefetch

        int k = 0;
        for (; k + 1 < m; k += 2) {
            const int e0 = __shfl_sync(FULL, es.x, k);
            const int s0 = __shfl_sync(FULL, es.y, k);
            const int e1 = __shfl_sync(FULL, es.x, k + 1);
            const int s1 = __shfl_sync(FULL, es.y, k + 1);
            edge_accum(e0, s0, lane, attr, w, p0, p1a, p1b, p1c, p2a, p2b, p2c);
            edge_accum(e1, s1, lane, attr, w, q0, q1a, q1b, q1c, q2a, q2b, q2c);
        }
        if (k < m) {
            const int e0 = __shfl_sync(FULL, es.x, k);
            const int s0 = __shfl_sync(FULL, es.y, k);
            edge_accum(e0, s0, lane, attr, w, p0, p1a, p1b, p1c, p2a, p2b, p2c);
        }
    }

    // Spill handling (uniform branch; g_spill_cnt == 0 on valid inputs).
    const int sp = g_spill_cnt;
    if (sp > 0) {
        const int lim = sp < SPILL_CAP ? sp : SPILL_CAP;
        for (int i = 0; i < lim; i++) {
            int4 sv = g_spill[i];
            if (sv.y == n)
                edge_accum(sv.x, sv.z, lane, attr, w, p0, p1a, p1b, p1c, p2a, p2b, p2c);
        }
    }

    const float o0  = INV_S2f * (p0 + q0);
    const float o1a = INV_S2f * (p1a + q1a);
    const float o1b = INV_S2f * (p1b + q1b);
    const float o1c = INV_S2f * (p1c + q1c);
    const float o2a = INV_S2f * (p2a + q2a);
    const float o2b = INV_S2f * (p2b + q2b);
    const float o2c = INV_S2f * (p2c + q2c);

    float* __restrict__ ob = out + (size_t)n * E_FEAT;
    ob[lane]               = o0;
    ob[32 + lane * 3 + 0]  = o1a;
    ob[32 + lane * 3 + 1]  = o1b;
    ob[32 + lane * 3 + 2]  = o1c;
    ob[128 + lane * 3 + 0] = o2a;
    ob[128 + lane * 3 + 1] = o2b;
    ob[128 + lane * 3 + 2] = o2c;
}

// ── fallback (E > MAX_E): round-4 atomic path (keeps its own full reset) ──

__device__ __forceinline__ void red_add_v4(float* addr, float4 v) {
    asm volatile("red.global.add.v4.f32 [%0], {%1,%2,%3,%4};"
                 :: "l"(addr), "f"(v.x), "f"(v.y), "f"(v.z), "f"(v.w)
                 : "memory");
}

__global__ void k_zero(float4* __restrict__ out, int n4) {
    int i = blockIdx.x * blockDim.x + threadIdx.x;
    if (i < n4) out[i] = make_float4(0.f, 0.f, 0.f, 0.f);
}

__global__ __launch_bounds__(256)
void k_scatter_atomic(const float* __restrict__ x, const float* __restrict__ attr,
                      const float* __restrict__ w, const void* __restrict__ edge_dst,
                      const void* __restrict__ edge_src, float* __restrict__ out, int E) {
    __shared__ float sf[8][E_FEAT];
    const int warp = threadIdx.x >> 5, lane = threadIdx.x & 31;
    const int e = blockIdx.x * 8 + warp;
    if (e >= E) return;
    const int is64 = g_idx_is_64;
    const long long s = load_index(edge_src, e, is64);
    const long long d = load_index(edge_dst, e, is64);
    if ((unsigned long long)s >= (unsigned long long)N_NODES ||
        (unsigned long long)d >= (unsigned long long)N_NODES) return;
    const float* xr = x + s * (4 * MUL);
    const float xs0 = __ldg(xr + lane);
    const float x1a = __ldg(xr + 32 + lane * 3 + 0);
    const float x1b = __ldg(xr + 32 + lane * 3 + 1);
    const float x1c = __ldg(xr + 32 + lane * 3 + 2);
    const float4 a = __ldcs(reinterpret_cast<const float4*>(attr + (size_t)e * 4));
    const float* wr = w + (size_t)e * (5 * MUL);
    const float w0 = __ldcs(wr + lane), w1 = __ldcs(wr + 32 + lane),
                w2 = __ldcs(wr + 64 + lane), w3 = __ldcs(wr + 96 + lane),
                w4 = __ldcs(wr + 128 + lane);
    const float dot = x1a * a.y + x1b * a.z + x1c * a.w;
    sf[warp][lane]               = INV_S2f * (w0 * xs0 * a.x + w3 * (INV_S3f * dot));
    sf[warp][32 + lane * 3 + 0]  = INV_S2f * (w1 * xs0 * a.y + w2 * x1a * a.x);
    sf[warp][32 + lane * 3 + 1]  = INV_S2f * (w1 * xs0 * a.z + w2 * x1b * a.x);
    sf[warp][32 + lane * 3 + 2]  = INV_S2f * (w1 * xs0 * a.w + w2 * x1c * a.x);
    sf[warp][128 + lane * 3 + 0] = INV_S2f * w4 * (x1b * a.w - x1c * a.z);
    sf[warp][128 + lane * 3 + 1] = INV_S2f * w4 * (x1c * a.y - x1a * a.w);
    sf[warp][128 + lane * 3 + 2] = INV_S2f * w4 * (x1a * a.z - x1b * a.y);
    __syncwarp();
    float* ob = out + d * E_FEAT;
    float4 v0 = *reinterpret_cast<float4*>(&sf[warp][lane * 4]);
    red_add_v4(ob + lane * 4, v0);
    int idx = lane + 32;
    if (idx < 56) {
        float4 v1 = *reinterpret_cast<float4*>(&sf[warp][idx * 4]);
        red_add_v4(ob + idx * 4, v1);
    }
}

extern "C" void kernel_launch(void* const* d_in, const int* in_sizes, int n_in,
                              void* d_out, int out_size) {
    const float* x = nullptr;
    const float* edge_attr = nullptr;
    const float* edge_wt = nullptr;
    const void* e_dst = nullptr;
    const void* e_src = nullptr;

    long long sz_w = 0;
    for (int i = 0; i < n_in; i++)
        if ((long long)in_sizes[i] > sz_w) sz_w = in_sizes[i];

    const long long E_ll = sz_w / 160;
    const long long sz_attr = E_ll * 4;
    const long long sz_idx  = E_ll;

    for (int i = 0; i < n_in; i++) {
        long long sz = in_sizes[i];
        if (sz == sz_w && !edge_wt)            edge_wt   = (const float*)d_in[i];
        else if (sz == sz_attr && !edge_attr)  edge_attr = (const float*)d_in[i];
        else if (sz == sz_idx) {
            if (!e_dst)      e_dst = d_in[i];
            else if (!e_src) e_src = d_in[i];
        }
        else if (!x)                           x = (const float*)d_in[i];
    }

    float* out = (float*)d_out;
    const int E = (int)E_ll;

    if (E <= MAX_E) {
        k_detect<<<1, 32>>>((const unsigned int*)e_dst, (const unsigned int*)e_src);
        int pb = (E + 2047) / 2048;         // 8 edges/thread
        int tb = (N_NODES + 7) / 8;
        int gb = pb > tb ? pb : tb;
        k_place_transpose<<<gb, 256>>>(e_dst, e_src, x, E);
        k_gather<<<N_NODES, 32>>>(edge_attr, edge_wt, out);
    } else {
        k_detect<<<1, 32>>>((const unsigned int*)e_dst, (const unsigned int*)e_src);
        const int n4 = out_size / 4;
        k_zero<<<(n4 + 255) / 256, 256>>>((float4*)out, n4);
        k_scatter_atomic<<<(E + 7) / 8, 256>>>(x, edge_attr, edge_wt, e_dst, e_src, out, E);
    }
}

// round 15
// speedup vs baseline: 2.0358x; 2.0358x over previous
#include <cuda_runtime.h>
#include <cstdint>

#define MUL 32
#define N_NODES 50000
#define E_FEAT 224
#define CAP 64                    // bucket capacity per node (Poisson(16) max ~45)
#define SPILL_CAP 8192
#define MAX_E  2097152
#define INV_S2f 0.70710678118654752f
#define INV_S3f 0.57735026918962576f

__device__ int   g_idx_is_64;
__device__ int   g_cnt[N_NODES];             // per-node cursor / degree
__device__ int   g_spill_cnt;
__device__ int4  g_spill[SPILL_CAP];         // (e, dst, src, 0) overflow edges
__device__ int2  g_es[N_NODES * CAP];        // (edge id, src) bucket slots
__device__ float g_xt[N_NODES * 4 * MUL];    // x transposed: [xs0|x1a|x1b|x1c]

__device__ __forceinline__ long long load_index(const void* p, int e, int is64) {
    if (is64) return ((const long long*)p)[e];
    return (long long)(__ldcs((const int*)p + e));
}

// k0: reset cursors + spill count + detect index dtype
__global__ void k_reset(const unsigned int* __restrict__ dw,
                        const unsigned int* __restrict__ sw) {
    int i = blockIdx.x * blockDim.x + threadIdx.x;
    if (i < N_NODES) g_cnt[i] = 0;
    if (blockIdx.x == 0 && threadIdx.x == 0) {
        g_spill_cnt = 0;
        int is64 = 1;
        #pragma unroll
        for (int k = 0; k < 32; k++) {
            if (dw[2 * k + 1] != 0u || sw[2 * k + 1] != 0u) { is64 = 0; break; }
        }
        g_idx_is_64 = is64;
    }
}

// k1: bucket-place (edge,src) (4 edges/thread, ILP) + x transpose (warp/node).
__global__ __launch_bounds__(256)
void k_place_transpose(const void* __restrict__ edge_dst,
                       const void* __restrict__ edge_src,
                       const float* __restrict__ x, int E) {
    const int base = (blockIdx.x * blockDim.x + threadIdx.x) * 4;
    const int is64 = g_idx_is_64;
    #pragma unroll
    for (int k = 0; k < 4; k++) {
        int e = base + k;
        if (e < E) {
            long long d = load_index(edge_dst, e, is64);
            if ((unsigned long long)d < (unsigned long long)N_NODES) {
                long long s = load_index(edge_src, e, is64);
                int c = atomicAdd(&g_cnt[(int)d], 1);
                if (c < CAP) {
                    g_es[(int)d * CAP + c] = make_int2(e, (int)s);
                } else {
                    int sp = atomicAdd(&g_spill_cnt, 1);
                    if (sp < SPILL_CAP) g_spill[sp] = make_int4(e, (int)d, (int)s, 0);
                }
            }
        }
    }
    const int warp = threadIdx.x >> 5;
    const int lane = threadIdx.x & 31;
    const int n = blockIdx.x * 8 + warp;
    if (n < N_NODES) {
        const float* __restrict__ xr = x + (size_t)n * (4 * MUL);
        float xs0 = __ldcs(xr + lane);
        float x1a = __ldcs(xr + 32 + lane * 3 + 0);
        float x1b = __ldcs(xr + 32 + lane * 3 + 1);
        float x1c = __ldcs(xr + 32 + lane * 3 + 2);
        float* __restrict__ xt = g_xt + (size_t)n * (4 * MUL);
        xt[lane]      = xs0;
        xt[32 + lane] = x1a;
        xt[64 + lane] = x1b;
        xt[96 + lane] = x1c;
    }
}

__device__ __forceinline__ void edge_accum(
    int e, int s, int lane,
    const float* __restrict__ attr, const float* __restrict__ w,
    float& a0, float& a1a, float& a1b, float& a1c,
    float& a2a, float& a2b, float& a2c)
{
    const float* __restrict__ xr = g_xt + (size_t)s * (4 * MUL);
    const float xs0 = __ldg(xr + lane);
    const float x1a = __ldg(xr + 32 + lane);
    const float x1b = __ldg(xr + 64 + lane);
    const float x1c = __ldg(xr + 96 + lane);

    const float4 a = __ldg(reinterpret_cast<const float4*>(attr + (size_t)e * 4));

    const float* __restrict__ wr = w + (size_t)e * (5 * MUL);
    const float w0 = __ldcs(wr + lane);
    const float w1 = __ldcs(wr + 32 + lane);
    const float w2 = __ldcs(wr + 64 + lane);
    const float w3 = __ldcs(wr + 96 + lane);
    const float w4 = __ldcs(wr + 128 + lane);

    const float dot = x1a * a.y + x1b * a.z + x1c * a.w;
    a0  += w0 * xs0 * a.x + w3 * (INV_S3f * dot);
    a1a += w1 * xs0 * a.y + w2 * x1a * a.x;
    a1b += w1 * xs0 * a.z + w2 * x1b * a.x;
    a1c += w1 * xs0 * a.w + w2 * x1c * a.x;
    a2a += w4 * (x1b * a.w - x1c * a.z);
    a2b += w4 * (x1c * a.y - x1a * a.w);
    a2c += w4 * (x1a * a.z - x1b * a.y);
}

// k2: ONE WARP PER BLOCK gather (proven R13 body). Streaming output stores
// (__stcs): write-once data stops evicting g_xt/g_es from L2.
__global__ __launch_bounds__(32)
void k_gather(const float* __restrict__ attr,
              const float* __restrict__ w,
              float* __restrict__ out) {
    const unsigned FULL = 0xffffffffu;
    const int lane = threadIdx.x;
    const int n = blockIdx.x;
    if (n >= N_NODES) return;

    int deg = __ldg(&g_cnt[n]);
    if (deg > CAP) deg = CAP;           // overflow handled via spill scan
    const int2* __restrict__ bucket = g_es + (size_t)n * CAP;

    float p0 = 0.f, p1a = 0.f, p1b = 0.f, p1c = 0.f, p2a = 0.f, p2b = 0.f, p2c = 0.f;
    float q0 = 0.f, q1a = 0.f, q1b = 0.f, q1c = 0.f, q2a = 0.f, q2b = 0.f, q2c = 0.f;

    for (int base = 0; base < deg; base += 32) {
        int m = deg - base; if (m > 32) m = 32;
        int2 es = make_int2(0, 0);
        if (lane < m) es = __ldg(&bucket[base + lane]);   // coalesced prefetch

        int k = 0;
        for (; k + 1 < m; k += 2) {
            const int e0 = __shfl_sync(FULL, es.x, k);
            const int s0 = __shfl_sync(FULL, es.y, k);
            const int e1 = __shfl_sync(FULL, es.x, k + 1);
            const int s1 = __shfl_sync(FULL, es.y, k + 1);
            edge_accum(e0, s0, lane, attr, w, p0, p1a, p1b, p1c, p2a, p2b, p2c);
            edge_accum(e1, s1, lane, attr, w, q0, q1a, q1b, q1c, q2a, q2b, q2c);
        }
        if (k < m) {
            const int e0 = __shfl_sync(FULL, es.x, k);
            const int s0 = __shfl_sync(FULL, es.y, k);
            edge_accum(e0, s0, lane, attr, w, p0, p1a, p1b, p1c, p2a, p2b, p2c);
        }
    }

    // Spill handling (uniform branch; g_spill_cnt == 0 on valid inputs).
    const int sp = g_spill_cnt;
    if (sp > 0) {
        const int lim = sp < SPILL_CAP ? sp : SPILL_CAP;
        for (int i = 0; i < lim; i++) {
            int4 sv = g_spill[i];
            if (sv.y == n)
                edge_accum(sv.x, sv.z, lane, attr, w, p0, p1a, p1b, p1c, p2a, p2b, p2c);
        }
    }

    const float o0  = INV_S2f * (p0 + q0);
    const float o1a = INV_S2f * (p1a + q1a);
    const float o1b = INV_S2f * (p1b + q1b);
    const float o1c = INV_S2f * (p1c + q1c);
    const float o2a = INV_S2f * (p2a + q2a);
    const float o2b = INV_S2f * (p2b + q2b);
    const float o2c = INV_S2f * (p2c + q2c);

    float* __restrict__ ob = out + (size_t)n * E_FEAT;
    __stcs(ob + lane, o0);
    __stcs(ob + 32 + lane * 3 + 0, o1a);
    __stcs(ob + 32 + lane * 3 + 1, o1b);
    __stcs(ob + 32 + lane * 3 + 2, o1c);
    __stcs(ob + 128 + lane * 3 + 0, o2a);
    __stcs(ob + 128 + lane * 3 + 1, o2b);
    __stcs(ob + 128 + lane * 3 + 2, o2c);
}

// ── fallback (E > MAX_E): round-4 atomic path ──

__device__ __forceinline__ void red_add_v4(float* addr, float4 v) {
    asm volatile("red.global.add.v4.f32 [%0], {%1,%2,%3,%4};"
                 :: "l"(addr), "f"(v.x), "f"(v.y), "f"(v.z), "f"(v.w)
                 : "memory");
}

__global__ void k_zero(float4* __restrict__ out, int n4) {
    int i = blockIdx.x * blockDim.x + threadIdx.x;
    if (i < n4) out[i] = make_float4(0.f, 0.f, 0.f, 0.f);
}

__global__ __launch_bounds__(256)
void k_scatter_atomic(const float* __restrict__ x, const float* __restrict__ attr,
                      const float* __restrict__ w, const void* __restrict__ edge_dst,
                      const void* __restrict__ edge_src, float* __restrict__ out, int E) {
    __shared__ float sf[8][E_FEAT];
    const int warp = threadIdx.x >> 5, lane = threadIdx.x & 31;
    const int e = blockIdx.x * 8 + warp;
    if (e >= E) return;
    const int is64 = g_idx_is_64;
    const long long s = load_index(edge_src, e, is64);
    const long long d = load_index(edge_dst, e, is64);
    if ((unsigned long long)s >= (unsigned long long)N_NODES ||
        (unsigned long long)d >= (unsigned long long)N_NODES) return;
    const float* xr = x + s * (4 * MUL);
    const float xs0 = __ldg(xr + lane);
    const float x1a = __ldg(xr + 32 + lane * 3 + 0);
    const float x1b = __ldg(xr + 32 + lane * 3 + 1);
    const float x1c = __ldg(xr + 32 + lane * 3 + 2);
    const float4 a = __ldcs(reinterpret_cast<const float4*>(attr + (size_t)e * 4));
    const float* wr = w + (size_t)e * (5 * MUL);
    const float w0 = __ldcs(wr + lane), w1 = __ldcs(wr + 32 + lane),
                w2 = __ldcs(wr + 64 + lane), w3 = __ldcs(wr + 96 + lane),
                w4 = __ldcs(wr + 128 + lane);
    const float dot = x1a * a.y + x1b * a.z + x1c * a.w;
    sf[warp][lane]               = INV_S2f * (w0 * xs0 * a.x + w3 * (INV_S3f * dot));
    sf[warp][32 + lane * 3 + 0]  = INV_S2f * (w1 * xs0 * a.y + w2 * x1a * a.x);
    sf[warp][32 + lane * 3 + 1]  = INV_S2f * (w1 * xs0 * a.z + w2 * x1b * a.x);
    sf[warp][32 + lane * 3 + 2]  = INV_S2f * (w1 * xs0 * a.w + w2 * x1c * a.x);
    sf[warp][128 + lane * 3 + 0] = INV_S2f * w4 * (x1b * a.w - x1c * a.z);
    sf[warp][128 + lane * 3 + 1] = INV_S2f * w4 * (x1c * a.y - x1a * a.w);
    sf[warp][128 + lane * 3 + 2] = INV_S2f * w4 * (x1a * a.z - x1b * a.y);
    __syncwarp();
    float* ob = out + d * E_FEAT;
    float4 v0 = *reinterpret_cast<float4*>(&sf[warp][lane * 4]);
    red_add_v4(ob + lane * 4, v0);
    int idx = lane + 32;
    if (idx < 56) {
        float4 v1 = *reinterpret_cast<float4*>(&sf[warp][idx * 4]);
        red_add_v4(ob + idx * 4, v1);
    }
}

extern "C" void kernel_launch(void* const* d_in, const int* in_sizes, int n_in,
                              void* d_out, int out_size) {
    const float* x = nullptr;
    const float* edge_attr = nullptr;
    const float* edge_wt = nullptr;
    const void* e_dst = nullptr;
    const void* e_src = nullptr;

    long long sz_w = 0;
    for (int i = 0; i < n_in; i++)
        if ((long long)in_sizes[i] > sz_w) sz_w = in_sizes[i];

    const long long E_ll = sz_w / 160;
    const long long sz_attr = E_ll * 4;
    const long long sz_idx  = E_ll;

    for (int i = 0; i < n_in; i++) {
        long long sz = in_sizes[i];
        if (sz == sz_w && !edge_wt)            edge_wt   = (const float*)d_in[i];
        else if (sz == sz_attr && !edge_attr)  edge_attr = (const float*)d_in[i];
        else if (sz == sz_idx) {
            if (!e_dst)      e_dst = d_in[i];
            else if (!e_src) e_src = d_in[i];
        }
        else if (!x)                           x = (const float*)d_in[i];
    }

    float* out = (float*)d_out;
    const int E = (int)E_ll;

    if (E <= MAX_E) {
        k_reset<<<(N_NODES + 255) / 256, 256>>>((const unsigned int*)e_dst,
                                                (const unsigned int*)e_src);
        int pb = (E + 1023) / 1024;
        int tb = (N_NODES + 7) / 8;
        int gb = pb > tb ? pb : tb;
        k_place_transpose<<<gb, 256>>>(e_dst, e_src, x, E);
        k_gather<<<N_NODES, 32>>>(edge_attr, edge_wt, out);
    } else {
        k_reset<<<(N_NODES + 255) / 256, 256>>>((const unsigned int*)e_dst,
                                                (const unsigned int*)e_src);
        const int n4 = out_size / 4;
        k_zero<<<(n4 + 255) / 256, 256>>>((float4*)out, n4);
        k_scatter_atomic<<<(E + 7) / 8, 256>>>(x, edge_attr, edge_wt, e_dst, e_src, out, E);
    }
}